// round 14
// baseline (speedup 1.0000x reference)
#include <cuda_runtime.h>
#include <cuda_fp16.h>
#include <stdint.h>
#include <stddef.h>

#define NN    100000
#define EMAX  1600000
#define FIN   128
#define HD    64
#define CD    40
#define H2STRIDE 64   // h2t row stride in halves (128B-aligned rows, 40 used)

#define SCAN_BS   512
#define NB1       ((NN + SCAN_BS - 1) / SCAN_BS)   // 196
#define NMASKW    ((NN * HD) / 32)                  // 200,000 packed mask words
#define NMASKB    (NN * HD / 8)                     // 800,000 mask bytes

#define FLAG_A 1ULL
#define FLAG_P 2ULL

#define APAD 136    // halves per sA/sB row (128 + 8 pad -> conflict-free fragments)

// ---------------- scratch (static device globals; no allocation) ----------------
__device__ float    g_dinv[NN];
__device__ int      g_cnt [NN];
__device__ int      g_rowptr[NN + 1];
__device__ int      g_cursor[NN];
__device__ unsigned long long g_lb[NB1];           // decoupled-lookback {value<<2|flag}
__device__ int2     g_epak[EMAX];                  // {src, bitcast(dinv[src])}
__device__ uint32_t g_mask[NMASKW];                // packed dropout keep-bits
__device__ __half   g_h1  [(size_t)NN * HD];       // gemm1 out (fp16, gathered by pull64)
__device__ __half   g_h2t [(size_t)NN * H2STRIDE]; // pull64-fused-gemm2 out (fp16, padded rows)

// ---------------- threefry2x32 (bit-exact JAX partitionable path) ----------------
__device__ __forceinline__ uint32_t rotl32(uint32_t x, int d) {
    return __funnelshift_l(x, x, d);
}
__device__ __forceinline__ void tf_round(uint32_t& x0, uint32_t& x1, int r) {
    x0 += x1; x1 = rotl32(x1, r); x1 ^= x0;
}
__device__ __forceinline__ uint2 threefry_0_42(uint32_t x0, uint32_t x1) {
    const uint32_t k0 = 0u, k1 = 42u;
    const uint32_t k2 = 0u ^ 42u ^ 0x1BD11BDAu;
    x0 += k0; x1 += k1;
    tf_round(x0,x1,13); tf_round(x0,x1,15); tf_round(x0,x1,26); tf_round(x0,x1,6);
    x0 += k1; x1 += k2 + 1u;
    tf_round(x0,x1,17); tf_round(x0,x1,29); tf_round(x0,x1,16); tf_round(x0,x1,24);
    x0 += k2; x1 += k0 + 2u;
    tf_round(x0,x1,13); tf_round(x0,x1,15); tf_round(x0,x1,26); tf_round(x0,x1,6);
    x0 += k0; x1 += k1 + 3u;
    tf_round(x0,x1,17); tf_round(x0,x1,29); tf_round(x0,x1,16); tf_round(x0,x1,24);
    x0 += k1; x1 += k2 + 4u;
    tf_round(x0,x1,13); tf_round(x0,x1,15); tf_round(x0,x1,26); tf_round(x0,x1,6);
    x0 += k2; x1 += k0 + 5u;
    return make_uint2(x0, x1);
}

// ---------------- CSR: histogram (+ lb zeroing, folded to trim a launch) ----------------
__global__ void hist_kernel(const int* __restrict__ col, int* __restrict__ cnt,
                            unsigned long long* __restrict__ lb, int E) {
    int i = blockIdx.x * blockDim.x + threadIdx.x;
    if (i < NB1) lb[i] = 0;
    if (i < E) atomicAdd(&cnt[col[i]], 1);
}

// ---------------- CSR: single-pass decoupled-lookback scan (+dinv, +cursor) ----------------
__global__ void scanlb_kernel(const int* __restrict__ cnt, int* __restrict__ rowptr,
                              int* __restrict__ cursor, float* __restrict__ dinv,
                              unsigned long long* lb, int n, int E) {
    __shared__ int s[SCAN_BS];
    __shared__ int bprefix;
    const int tid = threadIdx.x, b = blockIdx.x;
    const int gid = b * SCAN_BS + tid;
    int v = (gid < n) ? cnt[gid] : 0;
    s[tid] = v;
    __syncthreads();
    #pragma unroll
    for (int off = 1; off < SCAN_BS; off <<= 1) {
        int t = (tid >= off) ? s[tid - off] : 0;
        __syncthreads();
        s[tid] += t;
        __syncthreads();
    }
    int total = s[SCAN_BS - 1];
    if (tid == 0) {
        if (b == 0) {
            *(volatile unsigned long long*)&lb[0] =
                ((unsigned long long)total << 2) | FLAG_P;
            bprefix = 0;
        } else {
            *(volatile unsigned long long*)&lb[b] =
                ((unsigned long long)total << 2) | FLAG_A;
            int running = 0;
            int i = b - 1;
            while (true) {
                unsigned long long w;
                do { w = *(volatile unsigned long long*)&lb[i]; } while ((w & 3ULL) == 0);
                if ((w & 3ULL) == FLAG_P) { running += (int)(w >> 2); break; }
                running += (int)(w >> 2);
                i--;
            }
            *(volatile unsigned long long*)&lb[b] =
                ((unsigned long long)(running + total) << 2) | FLAG_P;
            bprefix = running;
        }
    }
    __syncthreads();
    int excl = bprefix + s[tid] - v;
    if (gid < n) {
        rowptr[gid] = excl;
        cursor[gid] = excl;
        dinv[gid]   = (float)(1.0 / sqrt((double)(v + 1)));   // +1 self loop
    }
    if (gid == 0) rowptr[n] = E;
}

// ---------------- CSR fill + dropout mask precompute (fused, disjoint ranges) ----------------
__global__ void fillmask_kernel(const int* __restrict__ row, const int* __restrict__ col,
                                const float* __restrict__ dinv,
                                int* __restrict__ cursor, int2* __restrict__ epak,
                                uint32_t* __restrict__ mask, int E) {
    int e = blockIdx.x * blockDim.x + threadIdx.x;
    if (e < NMASKB) {           // one mask byte (8 elements) per thread
        const float KEEP = (float)(1.0 - 0.4144);
        uint32_t base = (uint32_t)e * 8u;
        uint32_t byte = 0;
        #pragma unroll
        for (int b = 0; b < 8; b++) {
            uint2 rnd = threefry_0_42(0u, base + (uint32_t)b);
            uint32_t bits = rnd.x ^ rnd.y;
            float u = __uint_as_float((bits >> 9) | 0x3f800000u) - 1.0f;
            byte |= (u < KEEP ? 1u : 0u) << b;
        }
        ((uint8_t*)mask)[e] = (uint8_t)byte;
    }
    if (e < E) {
        int r = row[e], c = col[e];
        int pos = atomicAdd(&cursor[c], 1);
        epak[pos] = make_int2(r, __float_as_int(dinv[r]));
    }
}

// ---------------- GEMM1 (tensor core): h1[n,64](fp16) = X[n,128] @ W1[128,64] ----------------
__global__ __launch_bounds__(256)
void gemm1_kernel(const float* __restrict__ X, const float* __restrict__ W,
                  __half* __restrict__ Y, int n) {
    __shared__ __half sA[64][APAD];   // X tile, row-major [m][k]
    __shared__ __half sB[64][APAD];   // W1 transposed [nCol][k]
    const int tid = threadIdx.x;
    const int m0  = blockIdx.x * 64;

    for (int i = tid; i < 64 * (FIN / 4); i += 256) {
        int rr = i >> 5;
        int kv = (i & 31) * 4;
        int rowg = m0 + rr;
        float4 v = (rowg < n) ? *(const float4*)&X[(size_t)rowg * FIN + kv]
                              : make_float4(0.f, 0.f, 0.f, 0.f);
        __half2 h0 = __floats2half2_rn(v.x, v.y);
        __half2 h1v = __floats2half2_rn(v.z, v.w);
        *(uint2*)&sA[rr][kv] = make_uint2(*(uint32_t*)&h0, *(uint32_t*)&h1v);
    }
    for (int i = tid; i < FIN * HD; i += 256) {
        int k = i >> 6, c = i & 63;
        sB[c][k] = __float2half_rn(W[i]);
    }
    __syncthreads();

    const int w    = tid >> 5;
    const int lane = tid & 31;
    const int mW = (w & 3) * 16;
    const int nW = (w >> 2) * 32;
    const int g  = lane >> 2;
    const int tg = lane & 3;

    float d[4][4];
    #pragma unroll
    for (int s = 0; s < 4; s++)
        d[s][0] = d[s][1] = d[s][2] = d[s][3] = 0.f;

    const uint32_t* rowA0 = (const uint32_t*)&sA[mW + g][0];
    const uint32_t* rowA8 = (const uint32_t*)&sA[mW + g + 8][0];

    #pragma unroll
    for (int ks = 0; ks < 8; ks++) {
        int k2 = ks * 8;
        uint32_t a0 = rowA0[k2 + tg];
        uint32_t a1 = rowA8[k2 + tg];
        uint32_t a2 = rowA0[k2 + tg + 4];
        uint32_t a3 = rowA8[k2 + tg + 4];
        #pragma unroll
        for (int s = 0; s < 4; s++) {
            const uint32_t* rowB = (const uint32_t*)&sB[nW + s * 8 + g][0];
            uint32_t b0 = rowB[k2 + tg];
            uint32_t b1 = rowB[k2 + tg + 4];
            asm volatile(
                "mma.sync.aligned.m16n8k16.row.col.f32.f16.f16.f32 "
                "{%0,%1,%2,%3}, {%4,%5,%6,%7}, {%8,%9}, {%0,%1,%2,%3};\n"
                : "+f"(d[s][0]), "+f"(d[s][1]), "+f"(d[s][2]), "+f"(d[s][3])
                : "r"(a0), "r"(a1), "r"(a2), "r"(a3), "r"(b0), "r"(b1));
        }
    }

    #pragma unroll
    for (int s = 0; s < 4; s++) {
        int c = nW + s * 8 + tg * 2;
        int r0 = m0 + mW + g;
        int r1 = r0 + 8;
        if (r0 < n) {
            __half2 p = __floats2half2_rn(d[s][0], d[s][1]);
            *(uint32_t*)&Y[(size_t)r0 * HD + c] = *(uint32_t*)&p;
        }
        if (r1 < n) {
            __half2 p = __floats2half2_rn(d[s][2], d[s][3]);
            *(uint32_t*)&Y[(size_t)r1 * HD + c] = *(uint32_t*)&p;
        }
    }
}

// ---------------- pull64 + relu + mask dropout + FUSED GEMM2 -> h2t fp16 (padded rows) ----------------
__global__ __launch_bounds__(256)
void pull64_kernel(const int* __restrict__ rowptr, const int2* __restrict__ epak,
                   const float* __restrict__ dinv, const __half* __restrict__ h,
                   const float* __restrict__ bias, const uint32_t* __restrict__ mask,
                   const float* __restrict__ W2, __half* __restrict__ out, int n) {
    __shared__ float sW2[HD][CD];     // 10KB
    __shared__ float sAr[8][HD + 2];  // per-warp staging of a-row
    const int tid = threadIdx.x;
    for (int i = tid; i < HD * CD; i += 256) sW2[i / CD][i % CD] = W2[i];
    __syncthreads();

    int wid  = (blockIdx.x * blockDim.x + tid) >> 5;
    int lane = tid & 31;
    int wl   = tid >> 5;
    if (wid >= n) return;
    const int node = wid;
    const __half2* hh = (const __half2*)h;         // 32 half2 per row
    float wn = dinv[node];
    float2 acc = *(const float2*)&bias[lane * 2];
    {
        float2 hv = __half22float2(hh[(size_t)node * 32 + lane]);
        acc.x += wn * wn * hv.x;
        acc.y += wn * wn * hv.y;
    }
    const int s = rowptr[node], e = rowptr[node + 1];
    for (int base = s; base < e; base += 32) {
        int m = min(32, e - base);
        int2 p = make_int2(0, 0);
        if (lane < m) p = epak[base + lane];       // ONE coalesced edge-record load
        for (int k0 = 0; k0 < m; k0 += 8) {
            int kb = min(8, m - k0);
            float  w[8];
            float2 v[8];
            #pragma unroll
            for (int k = 0; k < 8; k++) {          // issue all gathers (MLP=8)
                if (k < kb) {
                    int src = __shfl_sync(0xffffffffu, p.x, k0 + k);
                    w[k] = __int_as_float(__shfl_sync(0xffffffffu, p.y, k0 + k)) * wn;
                    v[k] = __half22float2(hh[(size_t)src * 32 + lane]);
                }
            }
            #pragma unroll
            for (int k = 0; k < 8; k++) {          // then accumulate
                if (k < kb) {
                    acc.x += w[k] * v[k].x;
                    acc.y += w[k] * v[k].y;
                }
            }
        }
    }
    // relu + dropout via precomputed bit mask
    const float KEEP = (float)(1.0 - 0.4144);
    uint32_t wbits = mask[node * 2 + (lane >> 4)];
    int b = (lane * 2) & 31;
    acc.x = (wbits >> b)       & 1u ? fmaxf(acc.x, 0.0f) / KEEP : 0.0f;
    acc.y = (wbits >> (b + 1)) & 1u ? fmaxf(acc.y, 0.0f) / KEEP : 0.0f;

    // fused gemm2: stage a-row, lanes 0..19 compute 2 output cols each
    *(float2*)&sAr[wl][lane * 2] = acc;
    __syncwarp();
    if (lane < CD / 2) {
        const int c0 = lane * 2;
        float2 o = make_float2(0.f, 0.f);
        #pragma unroll 8
        for (int k = 0; k < HD; k++) {
            float ak = sAr[wl][k];
            float2 wv = *(const float2*)&sW2[k][c0];
            o.x += ak * wv.x;
            o.y += ak * wv.y;
        }
        __half2 p = __floats2half2_rn(o.x, o.y);
        *(uint32_t*)&out[(size_t)node * H2STRIDE + c0] = *(uint32_t*)&p;
    }
}

// ---------------- pull40: MLP-8 edge gathers + log_softmax ----------------
__global__ __launch_bounds__(256)
void pull40_kernel(const int* __restrict__ rowptr, const int2* __restrict__ epak,
                   const float* __restrict__ dinv, const __half* __restrict__ h,
                   const float* __restrict__ bias, float* __restrict__ out, int n) {
    int wid  = (blockIdx.x * blockDim.x + threadIdx.x) >> 5;
    int lane = threadIdx.x & 31;
    if (wid >= n) return;
    const int node = wid;
    const bool act = lane < CD / 2;                    // 20 active lanes
    const __half2* hh = (const __half2*)h;             // H2STRIDE/2 = 32 half2 per row
    float wn = dinv[node];
    float2 acc = make_float2(0.f, 0.f);
    if (act) {
        acc = *(const float2*)&bias[lane * 2];
        float2 hv = __half22float2(hh[(size_t)node * 32 + lane]);
        acc.x += wn * wn * hv.x;
        acc.y += wn * wn * hv.y;
    }
    const int s = rowptr[node], e = rowptr[node + 1];
    for (int base = s; base < e; base += 32) {
        int m = min(32, e - base);
        int2 p = make_int2(0, 0);
        if (lane < m) p = epak[base + lane];
        for (int k0 = 0; k0 < m; k0 += 8) {
            int kb = min(8, m - k0);
            float  w[8];
            float2 v[8];
            #pragma unroll
            for (int k = 0; k < 8; k++) {
                if (k < kb) {
                    int src = __shfl_sync(0xffffffffu, p.x, k0 + k);
                    w[k] = __int_as_float(__shfl_sync(0xffffffffu, p.y, k0 + k)) * wn;
                    if (act) v[k] = __half22float2(hh[(size_t)src * 32 + lane]);
                }
            }
            #pragma unroll
            for (int k = 0; k < 8; k++) {
                if (k < kb && act) {
                    acc.x += w[k] * v[k].x;
                    acc.y += w[k] * v[k].y;
                }
            }
        }
    }
    float m = act ? fmaxf(acc.x, acc.y) : -3.4e38f;
    #pragma unroll
    for (int o = 16; o; o >>= 1) m = fmaxf(m, __shfl_xor_sync(0xffffffffu, m, o));
    float sE = act ? (expf(acc.x - m) + expf(acc.y - m)) : 0.0f;
    #pragma unroll
    for (int o = 16; o; o >>= 1) sE += __shfl_xor_sync(0xffffffffu, sE, o);
    float ls = logf(sE);
    if (act)
        *(float2*)&out[(size_t)node * CD + lane * 2] =
            make_float2(acc.x - m - ls, acc.y - m - ls);
}

// ---------------- launch ----------------
extern "C" void kernel_launch(void* const* d_in, const int* in_sizes, int n_in,
                              void* d_out, int out_size) {
    const float* x  = (const float*)d_in[0];
    const int*   ei = (const int*)  d_in[1];
    const float* W1 = (const float*)d_in[2];
    const float* b1 = (const float*)d_in[3];
    const float* W2 = (const float*)d_in[4];
    const float* b2 = (const float*)d_in[5];
    float* out = (float*)d_out;

    const int n = NN;
    const int E = in_sizes[1] / 2;
    const int* row = ei;
    const int* col = ei + E;

    float *dinv;
    __half *h1, *h2t;
    int *cnt, *rowptr, *cursor;
    unsigned long long *lb;
    int2 *epak;
    uint32_t *mask;
    cudaGetSymbolAddress((void**)&dinv,   g_dinv);
    cudaGetSymbolAddress((void**)&cnt,    g_cnt);
    cudaGetSymbolAddress((void**)&rowptr, g_rowptr);
    cudaGetSymbolAddress((void**)&cursor, g_cursor);
    cudaGetSymbolAddress((void**)&lb,     g_lb);
    cudaGetSymbolAddress((void**)&epak,   g_epak);
    cudaGetSymbolAddress((void**)&mask,   g_mask);
    cudaGetSymbolAddress((void**)&h1,     g_h1);
    cudaGetSymbolAddress((void**)&h2t,    g_h2t);

    static cudaStream_t s_csr = 0;
    static cudaEvent_t  e_fork = 0, e_join = 0;
    if (!s_csr) {
        cudaStreamCreateWithFlags(&s_csr, cudaStreamNonBlocking);
        cudaEventCreateWithFlags(&e_fork, cudaEventDisableTiming);
        cudaEventCreateWithFlags(&e_join, cudaEventDisableTiming);
    }

    const int T = 256;
    auto cdiv = [](long long a, long long b) { return (int)((a + b - 1) / b); };

    // ---- fork: CSR build + dropout mask on side stream, gemm1 on main stream ----
    cudaEventRecord(e_fork, 0);
    cudaStreamWaitEvent(s_csr, e_fork, 0);

    cudaMemsetAsync(cnt, 0, NN * sizeof(int), s_csr);
    hist_kernel    <<<cdiv(E, T), T, 0, s_csr>>>(col, cnt, lb, E);
    scanlb_kernel  <<<NB1, SCAN_BS, 0, s_csr>>>(cnt, rowptr, cursor, dinv, lb, n, E);
    fillmask_kernel<<<cdiv(E, T), T, 0, s_csr>>>(row, col, dinv, cursor, epak, mask, E);
    cudaEventRecord(e_join, s_csr);

    gemm1_kernel<<<cdiv(n, 64), 256>>>(x, W1, h1, n);

    // ---- join, then the dependent chain on the main stream ----
    cudaStreamWaitEvent(0, e_join, 0);
    pull64_kernel<<<cdiv((long long)n * 32, T), T>>>(rowptr, epak, dinv, h1, b1, mask, W2, h2t, n);
    pull40_kernel<<<cdiv((long long)n * 32, T), T>>>(rowptr, epak, dinv, h2t, b2, out, n);
}

// round 15
// speedup vs baseline: 1.4474x; 1.4474x over previous
#include <cuda_runtime.h>
#include <cuda_fp16.h>
#include <stdint.h>
#include <stddef.h>

#define NN    100000
#define EMAX  1600000
#define FIN   128
#define HD    64
#define CD    40
#define H2STRIDE 64   // h2t row stride in halves (128B-aligned rows, 40 used)

#define SCAN_BS   512
#define NB1       ((NN + SCAN_BS - 1) / SCAN_BS)   // 196
#define NMASKW    ((NN * HD) / 32)                  // 200,000 packed mask words
#define NMASKB    (NN * HD / 8)                     // 800,000 mask bytes

#define FLAG_A 1ULL
#define FLAG_P 2ULL

#define APAD 136    // halves per sA/sB row (128 + 8 pad -> conflict-free fragments)

// ---------------- scratch (static device globals; no allocation) ----------------
__device__ float    g_dinv[NN];
__device__ int      g_cnt [NN];
__device__ int      g_rowptr[NN + 1];
__device__ int      g_cursor[NN];
__device__ unsigned long long g_lb[NB1];           // decoupled-lookback {value<<2|flag}
__device__ int2     g_epak[EMAX];                  // {src, bitcast(dinv[src])}
__device__ uint32_t g_mask[NMASKW];                // packed dropout keep-bits
__device__ __half   g_h1  [(size_t)NN * HD];       // gemm1 out (fp16, gathered by pull64)
__device__ __half   g_h2t [(size_t)NN * H2STRIDE]; // pull64-fused-gemm2 out (fp16, padded rows)

// ---------------- threefry2x32 (bit-exact JAX partitionable path) ----------------
__device__ __forceinline__ uint32_t rotl32(uint32_t x, int d) {
    return __funnelshift_l(x, x, d);
}
__device__ __forceinline__ void tf_round(uint32_t& x0, uint32_t& x1, int r) {
    x0 += x1; x1 = rotl32(x1, r); x1 ^= x0;
}
__device__ __forceinline__ uint2 threefry_0_42(uint32_t x0, uint32_t x1) {
    const uint32_t k0 = 0u, k1 = 42u;
    const uint32_t k2 = 0u ^ 42u ^ 0x1BD11BDAu;
    x0 += k0; x1 += k1;
    tf_round(x0,x1,13); tf_round(x0,x1,15); tf_round(x0,x1,26); tf_round(x0,x1,6);
    x0 += k1; x1 += k2 + 1u;
    tf_round(x0,x1,17); tf_round(x0,x1,29); tf_round(x0,x1,16); tf_round(x0,x1,24);
    x0 += k2; x1 += k0 + 2u;
    tf_round(x0,x1,13); tf_round(x0,x1,15); tf_round(x0,x1,26); tf_round(x0,x1,6);
    x0 += k0; x1 += k1 + 3u;
    tf_round(x0,x1,17); tf_round(x0,x1,29); tf_round(x0,x1,16); tf_round(x0,x1,24);
    x0 += k1; x1 += k2 + 4u;
    tf_round(x0,x1,13); tf_round(x0,x1,15); tf_round(x0,x1,26); tf_round(x0,x1,6);
    x0 += k2; x1 += k0 + 5u;
    return make_uint2(x0, x1);
}

// ---------------- CSR: histogram (+ lb zeroing folded) ----------------
__global__ void hist_kernel(const int* __restrict__ col, int* __restrict__ cnt,
                            unsigned long long* __restrict__ lb, int E) {
    int i = blockIdx.x * blockDim.x + threadIdx.x;
    if (i < NB1) lb[i] = 0;
    if (i < E) atomicAdd(&cnt[col[i]], 1);
}

// ---------------- CSR: single-pass decoupled-lookback scan (+dinv, +cursor) ----------------
__global__ void scanlb_kernel(const int* __restrict__ cnt, int* __restrict__ rowptr,
                              int* __restrict__ cursor, float* __restrict__ dinv,
                              unsigned long long* lb, int n, int E) {
    __shared__ int s[SCAN_BS];
    __shared__ int bprefix;
    const int tid = threadIdx.x, b = blockIdx.x;
    const int gid = b * SCAN_BS + tid;
    int v = (gid < n) ? cnt[gid] : 0;
    s[tid] = v;
    __syncthreads();
    #pragma unroll
    for (int off = 1; off < SCAN_BS; off <<= 1) {
        int t = (tid >= off) ? s[tid - off] : 0;
        __syncthreads();
        s[tid] += t;
        __syncthreads();
    }
    int total = s[SCAN_BS - 1];
    if (tid == 0) {
        if (b == 0) {
            *(volatile unsigned long long*)&lb[0] =
                ((unsigned long long)total << 2) | FLAG_P;
            bprefix = 0;
        } else {
            *(volatile unsigned long long*)&lb[b] =
                ((unsigned long long)total << 2) | FLAG_A;
            int running = 0;
            int i = b - 1;
            while (true) {
                unsigned long long w;
                do { w = *(volatile unsigned long long*)&lb[i]; } while ((w & 3ULL) == 0);
                if ((w & 3ULL) == FLAG_P) { running += (int)(w >> 2); break; }
                running += (int)(w >> 2);
                i--;
            }
            *(volatile unsigned long long*)&lb[b] =
                ((unsigned long long)(running + total) << 2) | FLAG_P;
            bprefix = running;
        }
    }
    __syncthreads();
    int excl = bprefix + s[tid] - v;
    if (gid < n) {
        rowptr[gid] = excl;
        cursor[gid] = excl;
        dinv[gid]   = (float)(1.0 / sqrt((double)(v + 1)));   // +1 self loop
    }
    if (gid == 0) rowptr[n] = E;
}

// ---------------- CSR fill + dropout mask precompute (fused, disjoint ranges) ----------------
__global__ void fillmask_kernel(const int* __restrict__ row, const int* __restrict__ col,
                                const float* __restrict__ dinv,
                                int* __restrict__ cursor, int2* __restrict__ epak,
                                uint32_t* __restrict__ mask, int E) {
    int e = blockIdx.x * blockDim.x + threadIdx.x;
    if (e < NMASKB) {           // one mask byte (8 elements) per thread
        const float KEEP = (float)(1.0 - 0.4144);
        uint32_t base = (uint32_t)e * 8u;
        uint32_t byte = 0;
        #pragma unroll
        for (int b = 0; b < 8; b++) {
            uint2 rnd = threefry_0_42(0u, base + (uint32_t)b);
            uint32_t bits = rnd.x ^ rnd.y;
            float u = __uint_as_float((bits >> 9) | 0x3f800000u) - 1.0f;
            byte |= (u < KEEP ? 1u : 0u) << b;
        }
        ((uint8_t*)mask)[e] = (uint8_t)byte;
    }
    if (e < E) {
        int r = row[e], c = col[e];
        int pos = atomicAdd(&cursor[c], 1);
        epak[pos] = make_int2(r, __float_as_int(dinv[r]));
    }
}

// ---------------- GEMM1 (tensor core): h1[n,64](fp16) = X[n,128] @ W1[128,64] ----------------
__global__ __launch_bounds__(256)
void gemm1_kernel(const float* __restrict__ X, const float* __restrict__ W,
                  __half* __restrict__ Y, int n) {
    __shared__ __half sA[64][APAD];   // X tile, row-major [m][k]
    __shared__ __half sB[64][APAD];   // W1 transposed [nCol][k]
    const int tid = threadIdx.x;
    const int m0  = blockIdx.x * 64;

    for (int i = tid; i < 64 * (FIN / 4); i += 256) {
        int rr = i >> 5;
        int kv = (i & 31) * 4;
        int rowg = m0 + rr;
        float4 v = (rowg < n) ? *(const float4*)&X[(size_t)rowg * FIN + kv]
                              : make_float4(0.f, 0.f, 0.f, 0.f);
        __half2 h0 = __floats2half2_rn(v.x, v.y);
        __half2 h1v = __floats2half2_rn(v.z, v.w);
        *(uint2*)&sA[rr][kv] = make_uint2(*(uint32_t*)&h0, *(uint32_t*)&h1v);
    }
    for (int i = tid; i < FIN * HD; i += 256) {
        int k = i >> 6, c = i & 63;
        sB[c][k] = __float2half_rn(W[i]);
    }
    __syncthreads();

    const int w    = tid >> 5;
    const int lane = tid & 31;
    const int mW = (w & 3) * 16;
    const int nW = (w >> 2) * 32;
    const int g  = lane >> 2;
    const int tg = lane & 3;

    float d[4][4];
    #pragma unroll
    for (int s = 0; s < 4; s++)
        d[s][0] = d[s][1] = d[s][2] = d[s][3] = 0.f;

    const uint32_t* rowA0 = (const uint32_t*)&sA[mW + g][0];
    const uint32_t* rowA8 = (const uint32_t*)&sA[mW + g + 8][0];

    #pragma unroll
    for (int ks = 0; ks < 8; ks++) {
        int k2 = ks * 8;
        uint32_t a0 = rowA0[k2 + tg];
        uint32_t a1 = rowA8[k2 + tg];
        uint32_t a2 = rowA0[k2 + tg + 4];
        uint32_t a3 = rowA8[k2 + tg + 4];
        #pragma unroll
        for (int s = 0; s < 4; s++) {
            const uint32_t* rowB = (const uint32_t*)&sB[nW + s * 8 + g][0];
            uint32_t b0 = rowB[k2 + tg];
            uint32_t b1 = rowB[k2 + tg + 4];
            asm volatile(
                "mma.sync.aligned.m16n8k16.row.col.f32.f16.f16.f32 "
                "{%0,%1,%2,%3}, {%4,%5,%6,%7}, {%8,%9}, {%0,%1,%2,%3};\n"
                : "+f"(d[s][0]), "+f"(d[s][1]), "+f"(d[s][2]), "+f"(d[s][3])
                : "r"(a0), "r"(a1), "r"(a2), "r"(a3), "r"(b0), "r"(b1));
        }
    }

    #pragma unroll
    for (int s = 0; s < 4; s++) {
        int c = nW + s * 8 + tg * 2;
        int r0 = m0 + mW + g;
        int r1 = r0 + 8;
        if (r0 < n) {
            __half2 p = __floats2half2_rn(d[s][0], d[s][1]);
            *(uint32_t*)&Y[(size_t)r0 * HD + c] = *(uint32_t*)&p;
        }
        if (r1 < n) {
            __half2 p = __floats2half2_rn(d[s][2], d[s][3]);
            *(uint32_t*)&Y[(size_t)r1 * HD + c] = *(uint32_t*)&p;
        }
    }
}

// ---------------- pull64 + relu + mask dropout + FUSED GEMM2 -> h2t fp16 (padded rows) ----------------
__global__ __launch_bounds__(256)
void pull64_kernel(const int* __restrict__ rowptr, const int2* __restrict__ epak,
                   const float* __restrict__ dinv, const __half* __restrict__ h,
                   const float* __restrict__ bias, const uint32_t* __restrict__ mask,
                   const float* __restrict__ W2, __half* __restrict__ out, int n) {
    __shared__ float sW2[HD][CD];     // 10KB
    __shared__ float sAr[8][HD + 2];  // per-warp staging of a-row
    const int tid = threadIdx.x;
    for (int i = tid; i < HD * CD; i += 256) sW2[i / CD][i % CD] = W2[i];
    __syncthreads();

    int wid  = (blockIdx.x * blockDim.x + tid) >> 5;
    int lane = tid & 31;
    int wl   = tid >> 5;
    if (wid >= n) return;
    const int node = wid;
    const __half2* hh = (const __half2*)h;         // 32 half2 per row
    float wn = dinv[node];
    float2 acc = *(const float2*)&bias[lane * 2];
    {
        float2 hv = __half22float2(hh[(size_t)node * 32 + lane]);
        acc.x += wn * wn * hv.x;
        acc.y += wn * wn * hv.y;
    }
    const int s = rowptr[node], e = rowptr[node + 1];
    for (int base = s; base < e; base += 32) {
        int m = min(32, e - base);
        int2 p = make_int2(0, 0);
        if (lane < m) p = epak[base + lane];       // ONE coalesced edge-record load
        for (int k = 0; k < m; k++) {
            int   src = __shfl_sync(0xffffffffu, p.x, k);
            float wv  = __int_as_float(__shfl_sync(0xffffffffu, p.y, k)) * wn;
            float2 v  = __half22float2(hh[(size_t)src * 32 + lane]);
            acc.x += wv * v.x;
            acc.y += wv * v.y;
        }
    }
    // relu + dropout via precomputed bit mask
    const float KEEP = (float)(1.0 - 0.4144);
    uint32_t wbits = mask[node * 2 + (lane >> 4)];
    int b = (lane * 2) & 31;
    acc.x = (wbits >> b)       & 1u ? fmaxf(acc.x, 0.0f) / KEEP : 0.0f;
    acc.y = (wbits >> (b + 1)) & 1u ? fmaxf(acc.y, 0.0f) / KEEP : 0.0f;

    // fused gemm2: stage a-row, lanes 0..19 compute 2 output cols each
    *(float2*)&sAr[wl][lane * 2] = acc;
    __syncwarp();
    if (lane < CD / 2) {
        const int c0 = lane * 2;
        float2 o = make_float2(0.f, 0.f);
        #pragma unroll 8
        for (int k = 0; k < HD; k++) {
            float ak = sAr[wl][k];
            float2 wv = *(const float2*)&sW2[k][c0];
            o.x += ak * wv.x;
            o.y += ak * wv.y;
        }
        __half2 p = __floats2half2_rn(o.x, o.y);
        *(uint32_t*)&out[(size_t)node * H2STRIDE + c0] = *(uint32_t*)&p;
    }
}

// ---------------- pull40: warp-cooperative edge staging + log_softmax (padded gather rows) ----------------
__global__ __launch_bounds__(256)
void pull40_kernel(const int* __restrict__ rowptr, const int2* __restrict__ epak,
                   const float* __restrict__ dinv, const __half* __restrict__ h,
                   const float* __restrict__ bias, float* __restrict__ out, int n) {
    int wid  = (blockIdx.x * blockDim.x + threadIdx.x) >> 5;
    int lane = threadIdx.x & 31;
    if (wid >= n) return;
    const int node = wid;
    const bool act = lane < CD / 2;                    // 20 active lanes
    const __half2* hh = (const __half2*)h;             // H2STRIDE/2 = 32 half2 per row
    float wn = dinv[node];
    float2 acc = make_float2(0.f, 0.f);
    if (act) {
        acc = *(const float2*)&bias[lane * 2];
        float2 hv = __half22float2(hh[(size_t)node * 32 + lane]);
        acc.x += wn * wn * hv.x;
        acc.y += wn * wn * hv.y;
    }
    const int s = rowptr[node], e = rowptr[node + 1];
    for (int base = s; base < e; base += 32) {
        int m = min(32, e - base);
        int2 p = make_int2(0, 0);
        if (lane < m) p = epak[base + lane];
        for (int k = 0; k < m; k++) {
            int   src = __shfl_sync(0xffffffffu, p.x, k);
            float w   = __int_as_float(__shfl_sync(0xffffffffu, p.y, k)) * wn;
            if (act) {
                float2 v = __half22float2(hh[(size_t)src * 32 + lane]);
                acc.x += w * v.x;
                acc.y += w * v.y;
            }
        }
    }
    float m = act ? fmaxf(acc.x, acc.y) : -3.4e38f;
    #pragma unroll
    for (int o = 16; o; o >>= 1) m = fmaxf(m, __shfl_xor_sync(0xffffffffu, m, o));
    float sE = act ? (expf(acc.x - m) + expf(acc.y - m)) : 0.0f;
    #pragma unroll
    for (int o = 16; o; o >>= 1) sE += __shfl_xor_sync(0xffffffffu, sE, o);
    float ls = logf(sE);
    if (act)
        *(float2*)&out[(size_t)node * CD + lane * 2] =
            make_float2(acc.x - m - ls, acc.y - m - ls);
}

// ---------------- launch ----------------
extern "C" void kernel_launch(void* const* d_in, const int* in_sizes, int n_in,
                              void* d_out, int out_size) {
    const float* x  = (const float*)d_in[0];
    const int*   ei = (const int*)  d_in[1];
    const float* W1 = (const float*)d_in[2];
    const float* b1 = (const float*)d_in[3];
    const float* W2 = (const float*)d_in[4];
    const float* b2 = (const float*)d_in[5];
    float* out = (float*)d_out;

    const int n = NN;
    const int E = in_sizes[1] / 2;
    const int* row = ei;
    const int* col = ei + E;

    float *dinv;
    __half *h1, *h2t;
    int *cnt, *rowptr, *cursor;
    unsigned long long *lb;
    int2 *epak;
    uint32_t *mask;
    cudaGetSymbolAddress((void**)&dinv,   g_dinv);
    cudaGetSymbolAddress((void**)&cnt,    g_cnt);
    cudaGetSymbolAddress((void**)&rowptr, g_rowptr);
    cudaGetSymbolAddress((void**)&cursor, g_cursor);
    cudaGetSymbolAddress((void**)&lb,     g_lb);
    cudaGetSymbolAddress((void**)&epak,   g_epak);
    cudaGetSymbolAddress((void**)&mask,   g_mask);
    cudaGetSymbolAddress((void**)&h1,     g_h1);
    cudaGetSymbolAddress((void**)&h2t,    g_h2t);

    static cudaStream_t s_csr = 0;
    static cudaEvent_t  e_fork = 0, e_join = 0;
    if (!s_csr) {
        cudaStreamCreateWithFlags(&s_csr, cudaStreamNonBlocking);
        cudaEventCreateWithFlags(&e_fork, cudaEventDisableTiming);
        cudaEventCreateWithFlags(&e_join, cudaEventDisableTiming);
    }

    const int T = 256;
    auto cdiv = [](long long a, long long b) { return (int)((a + b - 1) / b); };

    // ---- fork: CSR build + dropout mask on side stream, gemm1 on main stream ----
    cudaEventRecord(e_fork, 0);
    cudaStreamWaitEvent(s_csr, e_fork, 0);

    cudaMemsetAsync(cnt, 0, NN * sizeof(int), s_csr);
    hist_kernel    <<<cdiv(E, T), T, 0, s_csr>>>(col, cnt, lb, E);
    scanlb_kernel  <<<NB1, SCAN_BS, 0, s_csr>>>(cnt, rowptr, cursor, dinv, lb, n, E);
    fillmask_kernel<<<cdiv(E, T), T, 0, s_csr>>>(row, col, dinv, cursor, epak, mask, E);
    cudaEventRecord(e_join, s_csr);

    gemm1_kernel<<<cdiv(n, 64), 256>>>(x, W1, h1, n);

    // ---- join, then the dependent chain on the main stream ----
    cudaStreamWaitEvent(0, e_join, 0);
    pull64_kernel<<<cdiv((long long)n * 32, T), T>>>(rowptr, epak, dinv, h1, b1, mask, W2, h2t, n);
    pull40_kernel<<<cdiv((long long)n * 32, T), T>>>(rowptr, epak, dinv, h2t, b2, out, n);
}